// round 2
// baseline (speedup 1.0000x reference)
#include <cuda_runtime.h>
#include <math.h>

#define Nn 10000
#define Ee 160000
#define Ff 64

// ---------- device scratch (no allocations allowed) ----------
__device__ float g_emb[Nn * Ff];
__device__ float g_h0 [Nn * Ff];
__device__ float g_h1 [Nn * Ff];
__device__ float g_A0 [Nn * Ff];
__device__ float g_A1 [Nn * Ff];
__device__ float g_nf1[Nn * Ff];
__device__ float g_R1 [(size_t)Ee * Ff];   // l=0 radial channel for interaction 1

__device__ __forceinline__ float silu_f(float x) {
    return x / (1.0f + __expf(-x));
}

// ---------- per-node init: emb = attrs @ w_embed ; h0 = emb @ u0_up ; zero A buffers ----------
__global__ void node_init_kernel(const float* __restrict__ attrs,
                                 const float* __restrict__ w_embed,
                                 const float* __restrict__ u0_up)
{
    int n = blockIdx.x;
    int f = threadIdx.x;
    __shared__ float semb[64];

    float v = 0.f;
#pragma unroll
    for (int s = 0; s < 10; s++)
        v += attrs[n * 10 + s] * w_embed[s * 64 + f];
    semb[f] = v;
    g_emb[n * 64 + f] = v;
    g_A0[n * 64 + f] = 0.f;
    g_A1[n * 64 + f] = 0.f;
    __syncthreads();

    float h = 0.f;
#pragma unroll 8
    for (int g2 = 0; g2 < 64; g2++)
        h += semb[g2] * u0_up[g2 * 64 + f];
    g_h0[n * 64 + f] = h;
}

// ---------- edge kernel: bessel -> radial MLP (l=0 channel only) -> epilogue ----------
// MODE 0: message for interaction 0 (atomicAdd into g_A0 using g_h0)
// MODE 1: store R1 for interaction 1
template <int MODE>
__global__ void __launch_bounds__(128)
edge_kernel(const float* __restrict__ pos,
            const float* __restrict__ shifts,
            const int*   __restrict__ snd,
            const int*   __restrict__ rcv,
            const float* __restrict__ W1,   // [8,64]
            const float* __restrict__ W2,   // [64,64]
            const float* __restrict__ W3)   // [64,256]; we use cols 4*f (l=0)
{
    __shared__ float sW1[8 * 64];
    __shared__ float sW2[64 * 64];
    __shared__ float sW3[64 * 64];

    int tid = threadIdx.x;
    for (int i = tid; i < 512; i += 128)  sW1[i] = W1[i];
    for (int i = tid; i < 4096; i += 128) sW2[i] = W2[i];
    for (int i = tid; i < 4096; i += 128) sW3[i] = W3[(i >> 6) * 256 + (i & 63) * 4];
    __syncthreads();

    int e = blockIdx.x * 128 + tid;
    if (e >= Ee) return;

    int s = snd[e];
    int r = rcv[e];

    float dx = pos[3 * r + 0] - pos[3 * s + 0] + shifts[3 * e + 0];
    float dy = pos[3 * r + 1] - pos[3 * s + 1] + shifts[3 * e + 1];
    float dz = pos[3 * r + 2] - pos[3 * s + 2] + shifts[3 * e + 2];
    float rr = sqrtf(dx * dx + dy * dy + dz * dz);

    // bessel radial basis with polynomial cutoff (p = 5)
    float inv = 1.0f / (rr + 1e-9f);
    float xr  = rr * 0.1f;
    float xr2 = xr * xr;
    float x5  = xr2 * xr2 * xr;
    float env = 1.0f - 21.0f * x5 + 35.0f * x5 * xr - 15.0f * x5 * xr2;
    if (xr >= 1.0f) env = 0.0f;
    float scl   = 0.44721359549995793f * inv * env;  // sqrt(2/10) / (r+eps) * env
    float theta = 3.14159265358979323846f * xr;      // pi * r / RMAX

    float b[8];
#pragma unroll
    for (int k = 0; k < 8; k++)
        b[k] = scl * sinf((float)(k + 1) * theta);

    // fused layer1+layer2: t2[j] = sum_i silu(b . W1[:,i]) * W2[i][j]
    float t2[64];
#pragma unroll
    for (int j = 0; j < 64; j++) t2[j] = 0.f;

#pragma unroll 2
    for (int i = 0; i < 64; i++) {
        float v = 0.f;
#pragma unroll
        for (int p = 0; p < 8; p++)
            v += b[p] * sW1[p * 64 + i];
        v = silu_f(v);
#pragma unroll
        for (int j = 0; j < 64; j += 4) {
            float4 w = *(const float4*)&sW2[i * 64 + j];
            t2[j + 0] += v * w.x;
            t2[j + 1] += v * w.y;
            t2[j + 2] += v * w.z;
            t2[j + 3] += v * w.w;
        }
    }
#pragma unroll
    for (int j = 0; j < 64; j++) t2[j] = silu_f(t2[j]);

    // layer3 (linear) + epilogue, 4 outputs at a time
#pragma unroll 1
    for (int f = 0; f < 64; f += 4) {
        float ax = 0.f, ay = 0.f, az = 0.f, aw = 0.f;
#pragma unroll
        for (int j = 0; j < 64; j++) {
            float4 w = *(const float4*)&sW3[j * 64 + f];
            ax += t2[j] * w.x;
            ay += t2[j] * w.y;
            az += t2[j] * w.z;
            aw += t2[j] * w.w;
        }
        if (MODE == 1) {
            float4 o = make_float4(ax, ay, az, aw);
            *(float4*)&g_R1[(size_t)e * 64 + f] = o;
        } else {
            float4 h = *(const float4*)&g_h0[s * 64 + f];
            atomicAdd(&g_A0[r * 64 + f + 0], h.x * ax);
            atomicAdd(&g_A0[r * 64 + f + 1], h.y * ay);
            atomicAdd(&g_A0[r * 64 + f + 2], h.z * az);
            atomicAdd(&g_A0[r * 64 + f + 3], h.w * aw);
        }
    }
}

// ---------- message pass for interaction 1 (one thread per edge-feature) ----------
__global__ void msg1_kernel(const int* __restrict__ snd, const int* __restrict__ rcv)
{
    unsigned idx = blockIdx.x * 256u + threadIdx.x;
    if (idx >= (unsigned)Ee * 64u) return;
    int e = idx >> 6;
    int f = idx & 63;
    float m = g_h1[snd[e] * 64 + f] * g_R1[idx];
    atomicAdd(&g_A1[rcv[e] * 64 + f], m);
}

// ---------- interaction-0 epilogue per node + out0 + h1 ----------
__global__ void node1_kernel(const float* __restrict__ attrs,
                             const float* __restrict__ u0_mix,
                             const float* __restrict__ u0_sc,
                             const float* __restrict__ u0_prod,
                             const float* __restrict__ w_read0,
                             const float* __restrict__ u1_up,
                             float* __restrict__ out)
{
    int n = blockIdx.x;
    int g = threadIdx.x;
    __shared__ float sA[64], se[64], snf[64], sred[64];

    sA[g] = g_A0[n * 64 + g] * (1.0f / 16.0f);
    se[g] = g_emb[n * 64 + g];
    __syncthreads();

    int sp = 0;
#pragma unroll
    for (int s = 0; s < 10; s++)
        if (attrs[n * 10 + s] > 0.5f) sp = s;

    const float* Wsc = u0_sc + sp * 4096;
    float am = 0.f, sc = 0.f;
#pragma unroll 8
    for (int f = 0; f < 64; f++) {
        am += sA[f] * u0_mix[f * 64 + g];   // l=0 mix block
        sc += se[f] * Wsc[f * 64 + g];
    }
    float p0 = u0_prod[g], p1 = u0_prod[64 + g], p2 = u0_prod[128 + g];
    float B  = am * (p0 + p1 * am + p2 * am * am);
    float nf = B + sc;

    g_nf1[n * 64 + g] = nf;
    snf[g]  = nf;
    sred[g] = nf * w_read0[g];
    __syncthreads();

    float h = 0.f;
#pragma unroll 8
    for (int f = 0; f < 64; f++)
        h += snf[f] * u1_up[f * 64 + g];
    g_h1[n * 64 + g] = h;

    if (g == 0) {
        float t = 0.f;
        for (int i = 0; i < 64; i++) t += sred[i];
        out[n * 2 + 0] = t;
    }
}

// ---------- interaction-1 epilogue per node + out1 ----------
__global__ void node2_kernel(const float* __restrict__ attrs,
                             const float* __restrict__ u1_mix,
                             const float* __restrict__ u1_sc,
                             const float* __restrict__ u1_prod,
                             const float* __restrict__ w_mlp1,
                             const float* __restrict__ w_mlp2,
                             float* __restrict__ out)
{
    int n = blockIdx.x;
    int g = threadIdx.x;
    __shared__ float sA[64], snf1[64], snf2[64], sred[16];

    sA[g]   = g_A1[n * 64 + g] * (1.0f / 16.0f);
    snf1[g] = g_nf1[n * 64 + g];
    __syncthreads();

    int sp = 0;
#pragma unroll
    for (int s = 0; s < 10; s++)
        if (attrs[n * 10 + s] > 0.5f) sp = s;

    const float* Wsc = u1_sc + sp * 4096;
    float am = 0.f, sc = 0.f;
#pragma unroll 8
    for (int f = 0; f < 64; f++) {
        am += sA[f]   * u1_mix[f * 64 + g];
        sc += snf1[f] * Wsc[f * 64 + g];
    }
    float p0 = u1_prod[g], p1 = u1_prod[64 + g], p2 = u1_prod[128 + g];
    float nf2 = am * (p0 + p1 * am + p2 * am * am) + sc;
    snf2[g] = nf2;
    __syncthreads();

    if (g < 16) {
        float hv = 0.f;
#pragma unroll 8
        for (int f = 0; f < 64; f++)
            hv += snf2[f] * w_mlp1[f * 16 + g];
        sred[g] = silu_f(hv) * w_mlp2[g];
    }
    __syncthreads();
    if (g == 0) {
        float t = 0.f;
        for (int i = 0; i < 16; i++) t += sred[i];
        out[n * 2 + 1] = t;
    }
}

extern "C" void kernel_launch(void* const* d_in, const int* in_sizes, int n_in,
                              void* d_out, int out_size)
{
    const float* positions  = (const float*)d_in[0];
    const float* node_attrs = (const float*)d_in[1];
    const float* shifts     = (const float*)d_in[2];
    const int*   senders    = (const int*)  d_in[3];
    const int*   receivers  = (const int*)  d_in[4];
    const float* w_embed    = (const float*)d_in[5];

    // Disambiguate ordering: setup_inputs dict order puts the u1 block at 13
    // (size 4096 = u1_up); reference-signature order puts w_read0 (size 64) at 13.
    int i_u0 = 6, i_u1, i_read0, i_mlp1, i_mlp2;
    if (in_sizes[13] == 64) {        // signature order
        i_read0 = 13; i_u1 = 14; i_mlp1 = 21; i_mlp2 = 22;
    } else {                          // dict order
        i_u1 = 13; i_read0 = 20; i_mlp1 = 21; i_mlp2 = 22;
    }

    const float* u0_up   = (const float*)d_in[i_u0 + 0];
    const float* u0_r1   = (const float*)d_in[i_u0 + 1];
    const float* u0_r2   = (const float*)d_in[i_u0 + 2];
    const float* u0_r3   = (const float*)d_in[i_u0 + 3];
    const float* u0_mix  = (const float*)d_in[i_u0 + 4];
    const float* u0_sc   = (const float*)d_in[i_u0 + 5];
    const float* u0_prod = (const float*)d_in[i_u0 + 6];
    const float* u1_up   = (const float*)d_in[i_u1 + 0];
    const float* u1_r1   = (const float*)d_in[i_u1 + 1];
    const float* u1_r2   = (const float*)d_in[i_u1 + 2];
    const float* u1_r3   = (const float*)d_in[i_u1 + 3];
    const float* u1_mix  = (const float*)d_in[i_u1 + 4];
    const float* u1_sc   = (const float*)d_in[i_u1 + 5];
    const float* u1_prod = (const float*)d_in[i_u1 + 6];
    const float* w_read0 = (const float*)d_in[i_read0];
    const float* w_mlp1  = (const float*)d_in[i_mlp1];
    const float* w_mlp2  = (const float*)d_in[i_mlp2];

    float* out = (float*)d_out;

    node_init_kernel<<<Nn, 64>>>(node_attrs, w_embed, u0_up);
    edge_kernel<0><<<Ee / 128, 128>>>(positions, shifts, senders, receivers,
                                      u0_r1, u0_r2, u0_r3);
    edge_kernel<1><<<Ee / 128, 128>>>(positions, shifts, senders, receivers,
                                      u1_r1, u1_r2, u1_r3);
    node1_kernel<<<Nn, 64>>>(node_attrs, u0_mix, u0_sc, u0_prod, w_read0, u1_up, out);
    msg1_kernel<<<(Ee * 64 + 255) / 256, 256>>>(senders, receivers);
    node2_kernel<<<Nn, 64>>>(node_attrs, u1_mix, u1_sc, u1_prod, w_mlp1, w_mlp2, out);
}

// round 3
// speedup vs baseline: 1.0722x; 1.0722x over previous
#include <cuda_runtime.h>
#include <math.h>

#define Nn 10000
#define Ee 160000

// ---------- device scratch ----------
__device__ float g_emb[Nn * 64];
__device__ float g_h0 [Nn * 64];
__device__ float g_h1 [Nn * 64];
__device__ float g_A0 [Nn * 64];
__device__ float g_A1 [Nn * 64];
__device__ float g_nf1[Nn * 64];
__device__ float g_R1 [(size_t)Ee * 64];

typedef unsigned long long u64;

__device__ __forceinline__ u64 pack2(float lo, float hi) {
    u64 r; asm("mov.b64 %0, {%1, %2};" : "=l"(r) : "f"(lo), "f"(hi)); return r;
}
__device__ __forceinline__ void unpack2(u64 v, float &a, float &b) {
    asm("mov.b64 {%0, %1}, %2;" : "=f"(a), "=f"(b) : "l"(v));
}
__device__ __forceinline__ void fma2(u64 &d, u64 a, u64 b) {
    asm("fma.rn.f32x2 %0, %1, %2, %0;" : "+l"(d) : "l"(a), "l"(b));
}
__device__ __forceinline__ void red4(float* p, float a, float b, float c, float d) {
    asm volatile("red.global.add.v4.f32 [%0], {%1, %2, %3, %4};"
                 :: "l"(p), "f"(a), "f"(b), "f"(c), "f"(d) : "memory");
}
__device__ __forceinline__ float silu_f(float x) {
    return x / (1.0f + __expf(-x));
}

// ---------- node init: emb = attrs @ w_embed ; h0 = emb @ u0_up ; zero A ----------
__global__ void __launch_bounds__(256)
node_init_kernel(const float* __restrict__ attrs,
                 const float* __restrict__ w_embed,
                 const float* __restrict__ u0_up)
{
    __shared__ float sUp[4096];
    __shared__ float sWe[640];
    __shared__ float semb[256];
    int tid = threadIdx.x;
    for (int i = tid; i < 4096; i += 256) sUp[i] = u0_up[i];
    for (int i = tid; i < 640;  i += 256) sWe[i] = w_embed[i];
    __syncthreads();

    int n = blockIdx.x * 4 + (tid >> 6);
    int g = tid & 63;

    float v = 0.f;
#pragma unroll
    for (int s = 0; s < 10; s++)
        v += attrs[n * 10 + s] * sWe[s * 64 + g];
    semb[tid] = v;
    g_emb[n * 64 + g] = v;
    g_A0[n * 64 + g] = 0.f;
    g_A1[n * 64 + g] = 0.f;
    __syncthreads();

    const float* se = &semb[tid & 192];
    float h = 0.f;
#pragma unroll 8
    for (int f = 0; f < 64; f++)
        h += se[f] * sUp[f * 64 + g];
    g_h0[n * 64 + g] = h;
}

// ---------- fused edge kernel: bessel -> two radial MLPs (l=0 channel) ----------
// phase 0: message for interaction 0 (red.v4 into g_A0 using g_h0)
// phase 1: store R1 for interaction 1
__global__ void __launch_bounds__(256, 2)
edge_fused(const float* __restrict__ pos,
           const float* __restrict__ shifts,
           const int*   __restrict__ snd,
           const int*   __restrict__ rcv,
           const float* __restrict__ W1a, const float* __restrict__ W2a,
           const float* __restrict__ W3a,
           const float* __restrict__ W1b, const float* __restrict__ W2b,
           const float* __restrict__ W3b)
{
    __shared__ __align__(16) float sW1[512];
    __shared__ __align__(16) float sW2[4096];
    __shared__ __align__(16) float sW3[4096];

    int tid = threadIdx.x;
    int e = blockIdx.x * 256 + tid;   // grid covers exactly Ee

    int s = snd[e];
    int r = rcv[e];

    float dx = pos[3 * r + 0] - pos[3 * s + 0] + shifts[3 * e + 0];
    float dy = pos[3 * r + 1] - pos[3 * s + 1] + shifts[3 * e + 1];
    float dz = pos[3 * r + 2] - pos[3 * s + 2] + shifts[3 * e + 2];
    float rr = sqrtf(dx * dx + dy * dy + dz * dz);

    float inv = 1.0f / (rr + 1e-9f);
    float xr  = rr * 0.1f;
    float xr2 = xr * xr;
    float x5  = xr2 * xr2 * xr;
    float env = 1.0f - 21.0f * x5 + 35.0f * x5 * xr - 15.0f * x5 * xr2;
    if (xr >= 1.0f) env = 0.0f;
    float scl   = 0.44721359549995793f * inv * env;
    float theta = 3.14159265358979323846f * xr;

    float b[8];
#pragma unroll
    for (int k = 0; k < 8; k++)
        b[k] = scl * sinf((float)(k + 1) * theta);

#pragma unroll 1
    for (int phase = 0; phase < 2; phase++) {
        const float* W1 = phase ? W1b : W1a;
        const float* W2 = phase ? W2b : W2a;
        const float* W3 = phase ? W3b : W3a;
        for (int i = tid; i < 512;  i += 256) sW1[i] = W1[i];
        for (int i = tid; i < 4096; i += 256) sW2[i] = W2[i];
        for (int i = tid; i < 4096; i += 256) sW3[i] = W3[(i >> 6) * 256 + (i & 63) * 4];
        __syncthreads();

        // layer1 fused into layer2 i-loop; layer2 packed over j
        u64 t2p[32];
#pragma unroll
        for (int j = 0; j < 32; j++) t2p[j] = 0ull;

#pragma unroll 2
        for (int i = 0; i < 64; i++) {
            float v = 0.f;
#pragma unroll
            for (int p = 0; p < 8; p++)
                v += b[p] * sW1[p * 64 + i];
            v = silu_f(v);
            u64 vv = pack2(v, v);
            const ulonglong2* w = (const ulonglong2*)&sW2[i * 64];
#pragma unroll
            for (int j4 = 0; j4 < 16; j4++) {
                ulonglong2 ww = w[j4];
                fma2(t2p[2 * j4 + 0], vv, ww.x);
                fma2(t2p[2 * j4 + 1], vv, ww.y);
            }
        }
        float t2[64];
#pragma unroll
        for (int j = 0; j < 32; j++) {
            float a0, a1; unpack2(t2p[j], a0, a1);
            t2[2 * j + 0] = silu_f(a0);
            t2[2 * j + 1] = silu_f(a1);
        }

        // layer3 (linear) + epilogue, 16 outputs per chunk, packed over f
#pragma unroll 1
        for (int c = 0; c < 4; c++) {
            u64 acc[8];
#pragma unroll
            for (int k = 0; k < 8; k++) acc[k] = 0ull;
#pragma unroll 4
            for (int j = 0; j < 64; j++) {
                u64 vv = pack2(t2[j], t2[j]);
                const ulonglong2* w = (const ulonglong2*)&sW3[j * 64 + c * 16];
#pragma unroll
                for (int q = 0; q < 4; q++) {
                    ulonglong2 ww = w[q];
                    fma2(acc[2 * q + 0], vv, ww.x);
                    fma2(acc[2 * q + 1], vv, ww.y);
                }
            }
            float o[16];
#pragma unroll
            for (int k = 0; k < 8; k++) unpack2(acc[k], o[2 * k], o[2 * k + 1]);

            if (phase == 0) {
#pragma unroll
                for (int q = 0; q < 4; q++) {
                    float4 h = *(const float4*)&g_h0[s * 64 + c * 16 + q * 4];
                    red4(&g_A0[r * 64 + c * 16 + q * 4],
                         h.x * o[4 * q + 0], h.y * o[4 * q + 1],
                         h.z * o[4 * q + 2], h.w * o[4 * q + 3]);
                }
            } else {
#pragma unroll
                for (int q = 0; q < 4; q++) {
                    float4 ov = make_float4(o[4 * q + 0], o[4 * q + 1],
                                            o[4 * q + 2], o[4 * q + 3]);
                    *(float4*)&g_R1[(size_t)e * 64 + c * 16 + q * 4] = ov;
                }
            }
        }
        __syncthreads();
    }
}

// ---------- interaction-1 message: 16 threads per edge, vector reductions ----------
__global__ void __launch_bounds__(256)
msg1_kernel(const int* __restrict__ snd, const int* __restrict__ rcv)
{
    unsigned idx = blockIdx.x * 256u + threadIdx.x;   // Ee*16 total
    int e = idx >> 4;
    int q = (idx & 15) * 4;
    int s = snd[e];
    int r = rcv[e];
    float4 R = *(const float4*)&g_R1[(size_t)e * 64 + q];
    float4 h = *(const float4*)&g_h1[s * 64 + q];
    red4(&g_A1[r * 64 + q], h.x * R.x, h.y * R.y, h.z * R.z, h.w * R.w);
}

// ---------- interaction-0 epilogue + out0 + h1 ----------
__global__ void __launch_bounds__(256)
node1_kernel(const float* __restrict__ attrs,
             const float* __restrict__ u0_mix,
             const float* __restrict__ u0_sc,
             const float* __restrict__ u0_prod,
             const float* __restrict__ w_read0,
             const float* __restrict__ u1_up,
             float* __restrict__ out)
{
    __shared__ float sMix[4096];
    __shared__ float sUp1[4096];
    __shared__ float sA[256], semb[256], snf[256], sred[256];

    int tid = threadIdx.x;
    for (int i = tid; i < 4096; i += 256) sMix[i] = u0_mix[i];      // l=0 block
    for (int i = tid; i < 4096; i += 256) sUp1[i] = u1_up[i];

    int n = blockIdx.x * 4 + (tid >> 6);
    int g = tid & 63;
    int L = tid & 192;

    sA[tid]   = g_A0[n * 64 + g] * (1.0f / 16.0f);
    semb[tid] = g_emb[n * 64 + g];
    __syncthreads();

    int sp = 0;
#pragma unroll
    for (int s = 0; s < 10; s++)
        if (attrs[n * 10 + s] > 0.5f) sp = s;

    const float* Wsc = u0_sc + sp * 4096;
    float am = 0.f, sc = 0.f;
#pragma unroll 8
    for (int f = 0; f < 64; f++) {
        am += sA[L + f]   * sMix[f * 64 + g];
        sc += semb[L + f] * Wsc[f * 64 + g];
    }
    float p0 = u0_prod[g], p1 = u0_prod[64 + g], p2 = u0_prod[128 + g];
    float nf = am * (p0 + p1 * am + p2 * am * am) + sc;

    g_nf1[n * 64 + g] = nf;
    snf[tid]  = nf;
    sred[tid] = nf * w_read0[g];
    __syncthreads();

    float h = 0.f;
#pragma unroll 8
    for (int f = 0; f < 64; f++)
        h += snf[L + f] * sUp1[f * 64 + g];
    g_h1[n * 64 + g] = h;

    if (g == 0) {
        float t = 0.f;
#pragma unroll
        for (int i = 0; i < 64; i++) t += sred[L + i];
        out[n * 2 + 0] = t;
    }
}

// ---------- interaction-1 epilogue + out1 ----------
__global__ void __launch_bounds__(256)
node2_kernel(const float* __restrict__ attrs,
             const float* __restrict__ u1_mix,
             const float* __restrict__ u1_sc,
             const float* __restrict__ u1_prod,
             const float* __restrict__ w_mlp1,
             const float* __restrict__ w_mlp2,
             float* __restrict__ out)
{
    __shared__ float sMix[4096];
    __shared__ float sM1[1024];
    __shared__ float sA[256], snf1[256], snf2[256], sred[64];

    int tid = threadIdx.x;
    for (int i = tid; i < 4096; i += 256) sMix[i] = u1_mix[i];      // l=0 block
    for (int i = tid; i < 1024; i += 256) sM1[i]  = w_mlp1[i];

    int n = blockIdx.x * 4 + (tid >> 6);
    int g = tid & 63;
    int L = tid & 192;

    sA[tid]   = g_A1[n * 64 + g] * (1.0f / 16.0f);
    snf1[tid] = g_nf1[n * 64 + g];
    __syncthreads();

    int sp = 0;
#pragma unroll
    for (int s = 0; s < 10; s++)
        if (attrs[n * 10 + s] > 0.5f) sp = s;

    const float* Wsc = u1_sc + sp * 4096;
    float am = 0.f, sc = 0.f;
#pragma unroll 8
    for (int f = 0; f < 64; f++) {
        am += sA[L + f]   * sMix[f * 64 + g];
        sc += snf1[L + f] * Wsc[f * 64 + g];
    }
    float p0 = u1_prod[g], p1 = u1_prod[64 + g], p2 = u1_prod[128 + g];
    float nf2 = am * (p0 + p1 * am + p2 * am * am) + sc;
    snf2[tid] = nf2;
    __syncthreads();

    if (g < 16) {
        float hv = 0.f;
#pragma unroll 8
        for (int f = 0; f < 64; f++)
            hv += snf2[L + f] * sM1[f * 16 + g];
        sred[(L >> 2) + g] = silu_f(hv) * w_mlp2[g];
    }
    __syncthreads();
    if (g == 0) {
        float t = 0.f;
#pragma unroll
        for (int i = 0; i < 16; i++) t += sred[(L >> 2) + i];
        out[n * 2 + 1] = t;
    }
}

extern "C" void kernel_launch(void* const* d_in, const int* in_sizes, int n_in,
                              void* d_out, int out_size)
{
    const float* positions  = (const float*)d_in[0];
    const float* node_attrs = (const float*)d_in[1];
    const float* shifts     = (const float*)d_in[2];
    const int*   senders    = (const int*)  d_in[3];
    const int*   receivers  = (const int*)  d_in[4];
    const float* w_embed    = (const float*)d_in[5];

    int i_u0 = 6, i_u1, i_read0, i_mlp1, i_mlp2;
    if (in_sizes[13] == 64) {        // signature order
        i_read0 = 13; i_u1 = 14; i_mlp1 = 21; i_mlp2 = 22;
    } else {                          // dict order
        i_u1 = 13; i_read0 = 20; i_mlp1 = 21; i_mlp2 = 22;
    }

    const float* u0_r1   = (const float*)d_in[i_u0 + 1];
    const float* u0_r2   = (const float*)d_in[i_u0 + 2];
    const float* u0_r3   = (const float*)d_in[i_u0 + 3];
    const float* u0_mix  = (const float*)d_in[i_u0 + 4];
    const float* u0_sc   = (const float*)d_in[i_u0 + 5];
    const float* u0_prod = (const float*)d_in[i_u0 + 6];
    const float* u0_up   = (const float*)d_in[i_u0 + 0];
    const float* u1_up   = (const float*)d_in[i_u1 + 0];
    const float* u1_r1   = (const float*)d_in[i_u1 + 1];
    const float* u1_r2   = (const float*)d_in[i_u1 + 2];
    const float* u1_r3   = (const float*)d_in[i_u1 + 3];
    const float* u1_mix  = (const float*)d_in[i_u1 + 4];
    const float* u1_sc   = (const float*)d_in[i_u1 + 5];
    const float* u1_prod = (const float*)d_in[i_u1 + 6];
    const float* w_read0 = (const float*)d_in[i_read0];
    const float* w_mlp1  = (const float*)d_in[i_mlp1];
    const float* w_mlp2  = (const float*)d_in[i_mlp2];

    float* out = (float*)d_out;

    node_init_kernel<<<Nn / 4, 256>>>(node_attrs, w_embed, u0_up);
    edge_fused<<<Ee / 256, 256>>>(positions, shifts, senders, receivers,
                                  u0_r1, u0_r2, u0_r3, u1_r1, u1_r2, u1_r3);
    node1_kernel<<<Nn / 4, 256>>>(node_attrs, u0_mix, u0_sc, u0_prod,
                                  w_read0, u1_up, out);
    msg1_kernel<<<Ee * 16 / 256, 256>>>(senders, receivers);
    node2_kernel<<<Nn / 4, 256>>>(node_attrs, u1_mix, u1_sc, u1_prod,
                                  w_mlp1, w_mlp2, out);
}

// round 4
// speedup vs baseline: 1.2620x; 1.1771x over previous
#include <cuda_runtime.h>
#include <math.h>

#define Nn 10000
#define Ee 160000

// ---------- device scratch ----------
__device__ float g_emb[Nn * 64];
__device__ float g_h0 [Nn * 64];
__device__ float g_h1 [Nn * 64];
__device__ float g_A0 [Nn * 64];
__device__ float g_A1 [Nn * 64];
__device__ float g_nf1[Nn * 64];
__device__ float g_R1 [(size_t)Ee * 64];

typedef unsigned long long u64;

__device__ __forceinline__ u64 pack2(float lo, float hi) {
    u64 r; asm("mov.b64 %0, {%1, %2};" : "=l"(r) : "f"(lo), "f"(hi)); return r;
}
__device__ __forceinline__ void unpack2(u64 v, float &a, float &b) {
    asm("mov.b64 {%0, %1}, %2;" : "=f"(a), "=f"(b) : "l"(v));
}
__device__ __forceinline__ void fma2(u64 &d, u64 a, u64 b) {
    asm("fma.rn.f32x2 %0, %1, %2, %0;" : "+l"(d) : "l"(a), "l"(b));
}
__device__ __forceinline__ void red4(float* p, float a, float b, float c, float d) {
    asm volatile("red.global.add.v4.f32 [%0], {%1, %2, %3, %4};"
                 :: "l"(p), "f"(a), "f"(b), "f"(c), "f"(d) : "memory");
}
__device__ __forceinline__ float silu_f(float x) {
    return __fdividef(x, 1.0f + __expf(-x));
}

// ---------- node init ----------
__global__ void __launch_bounds__(256)
node_init_kernel(const float* __restrict__ attrs,
                 const float* __restrict__ w_embed,
                 const float* __restrict__ u0_up)
{
    __shared__ float sUp[4096];
    __shared__ float sWe[640];
    __shared__ float semb[256];
    int tid = threadIdx.x;
    for (int i = tid; i < 4096; i += 256) sUp[i] = u0_up[i];
    for (int i = tid; i < 640;  i += 256) sWe[i] = w_embed[i];
    __syncthreads();

    int n = blockIdx.x * 4 + (tid >> 6);
    int g = tid & 63;

    float v = 0.f;
#pragma unroll
    for (int s = 0; s < 10; s++)
        v += attrs[n * 10 + s] * sWe[s * 64 + g];
    semb[tid] = v;
    g_emb[n * 64 + g] = v;
    g_A0[n * 64 + g] = 0.f;
    g_A1[n * 64 + g] = 0.f;
    __syncthreads();

    const float* se = &semb[tid & 192];
    float h = 0.f;
#pragma unroll 8
    for (int f = 0; f < 64; f++)
        h += se[f] * sUp[f * 64 + g];
    g_h0[n * 64 + g] = h;
}

// ---------- fused edge kernel: tiled GEMM formulation ----------
// smem layout (dynamic, 100KB):
//   sAct[64][256]  64KB  activations, k-major
//   sWd [64][64]   32KB  weights duplicated as f32x2
//   sW1 [8][64]     2KB
//   sS, sR          2KB
__global__ void __launch_bounds__(256, 2)
edge_fused(const float* __restrict__ pos,
           const float* __restrict__ shifts,
           const int*   __restrict__ snd,
           const int*   __restrict__ rcv,
           const float* __restrict__ W1a, const float* __restrict__ W2a,
           const float* __restrict__ W3a,
           const float* __restrict__ W1b, const float* __restrict__ W2b,
           const float* __restrict__ W3b)
{
    extern __shared__ char smem_raw[];
    float* sAct = (float*)smem_raw;                    // 65536 B
    u64*   sWd  = (u64*)  (smem_raw + 65536);          // 32768 B
    float* sW1  = (float*)(smem_raw + 98304);          //  2048 B
    int*   sS   = (int*)  (smem_raw + 100352);         //  1024 B
    int*   sR   = (int*)  (smem_raw + 101376);         //  1024 B

    int tid = threadIdx.x;
    int e   = blockIdx.x * 256 + tid;

    int s = snd[e];
    int r = rcv[e];
    sS[tid] = s;
    sR[tid] = r;

    float dx = pos[3 * r + 0] - pos[3 * s + 0] + shifts[3 * e + 0];
    float dy = pos[3 * r + 1] - pos[3 * s + 1] + shifts[3 * e + 1];
    float dz = pos[3 * r + 2] - pos[3 * s + 2] + shifts[3 * e + 2];
    float rr = sqrtf(dx * dx + dy * dy + dz * dz);

    float inv = 1.0f / (rr + 1e-9f);
    float xr  = rr * 0.1f;
    float xr2 = xr * xr;
    float x5  = xr2 * xr2 * xr;
    float env = 1.0f - 21.0f * x5 + 35.0f * x5 * xr - 15.0f * x5 * xr2;
    if (xr >= 1.0f) env = 0.0f;
    float scl   = 0.44721359549995793f * inv * env;
    float theta = 3.14159265358979323846f * xr;

    float b[8];
#pragma unroll
    for (int k = 0; k < 8; k++)
        b[k] = scl * sinf((float)(k + 1) * theta);

    int tm = tid & 31;    // edge group: edges tm*8 .. tm*8+7
    int tn = tid >> 5;    // feature group: feats tn*8 .. tn*8+7

#pragma unroll 1
    for (int phase = 0; phase < 2; phase++) {
        const float* W1 = phase ? W1b : W1a;
        const float* W2 = phase ? W2b : W2a;
        const float* W3 = phase ? W3b : W3a;

        __syncthreads();   // prev phase fully done before overwriting smem
        for (int i = tid; i < 512; i += 256) sW1[i] = W1[i];
        for (int i = tid; i < 4096; i += 256) {
            float w = W2[i];
            sWd[i] = pack2(w, w);
        }
        __syncthreads();

        // ---- layer1: one edge per thread, write sAct[i][tid] ----
#pragma unroll 2
        for (int i = 0; i < 64; i++) {
            float v = 0.f;
#pragma unroll
            for (int p = 0; p < 8; p++)
                v += b[p] * sW1[p * 64 + i];
            sAct[i * 256 + tid] = silu_f(v);
        }
        __syncthreads();

        // ---- GEMM1: acc[n][m] = sum_k sAct[k][m] * W2[k][n] ----
        u64 acc[32];
#pragma unroll
        for (int i = 0; i < 32; i++) acc[i] = 0ull;

#pragma unroll 2
        for (int k = 0; k < 64; k++) {
            ulonglong2 a01 = *(const ulonglong2*)&sAct[k * 256 + tm * 8];
            ulonglong2 a23 = *(const ulonglong2*)&sAct[k * 256 + tm * 8 + 4];
            u64 am[4] = {a01.x, a01.y, a23.x, a23.y};
            const ulonglong2* wp = (const ulonglong2*)&sWd[k * 64 + tn * 8];
            ulonglong2 w01 = wp[0], w23 = wp[1], w45 = wp[2], w67 = wp[3];
            u64 wn[8] = {w01.x, w01.y, w23.x, w23.y, w45.x, w45.y, w67.x, w67.y};
#pragma unroll
            for (int n = 0; n < 8; n++)
#pragma unroll
                for (int mp = 0; mp < 4; mp++)
                    fma2(acc[n * 4 + mp], am[mp], wn[n]);
        }
        __syncthreads();   // all GEMM1 reads of sAct/sWd complete

        // ---- silu + transposed writeback; load W3 (l=0 cols) ----
#pragma unroll
        for (int n = 0; n < 8; n++) {
            float f0, f1, f2, f3, f4, f5, f6, f7;
            unpack2(acc[n * 4 + 0], f0, f1);
            unpack2(acc[n * 4 + 1], f2, f3);
            unpack2(acc[n * 4 + 2], f4, f5);
            unpack2(acc[n * 4 + 3], f6, f7);
            float4 lo = make_float4(silu_f(f0), silu_f(f1), silu_f(f2), silu_f(f3));
            float4 hi = make_float4(silu_f(f4), silu_f(f5), silu_f(f6), silu_f(f7));
            *(float4*)&sAct[(tn * 8 + n) * 256 + tm * 8]     = lo;
            *(float4*)&sAct[(tn * 8 + n) * 256 + tm * 8 + 4] = hi;
        }
        for (int i = tid; i < 4096; i += 256) {
            float w = W3[(i >> 6) * 256 + (i & 63) * 4];
            sWd[i] = pack2(w, w);
        }
        __syncthreads();

        // ---- GEMM2 (linear) ----
#pragma unroll
        for (int i = 0; i < 32; i++) acc[i] = 0ull;
#pragma unroll 2
        for (int k = 0; k < 64; k++) {
            ulonglong2 a01 = *(const ulonglong2*)&sAct[k * 256 + tm * 8];
            ulonglong2 a23 = *(const ulonglong2*)&sAct[k * 256 + tm * 8 + 4];
            u64 am[4] = {a01.x, a01.y, a23.x, a23.y};
            const ulonglong2* wp = (const ulonglong2*)&sWd[k * 64 + tn * 8];
            ulonglong2 w01 = wp[0], w23 = wp[1], w45 = wp[2], w67 = wp[3];
            u64 wn[8] = {w01.x, w01.y, w23.x, w23.y, w45.x, w45.y, w67.x, w67.y};
#pragma unroll
            for (int n = 0; n < 8; n++)
#pragma unroll
                for (int mp = 0; mp < 4; mp++)
                    fma2(acc[n * 4 + mp], am[mp], wn[n]);
        }

        // ---- epilogue: 8 edges x 8 feats per thread ----
        if (phase == 0) {
#pragma unroll
            for (int j = 0; j < 8; j++) {
                int em = tm * 8 + j;
                int ss = sS[em];
                int rr2 = sR[em];
                float o[8];
#pragma unroll
                for (int n = 0; n < 8; n++) {
                    float lo, hi;
                    unpack2(acc[n * 4 + (j >> 1)], lo, hi);
                    o[n] = (j & 1) ? hi : lo;
                }
                float4 ha = *(const float4*)&g_h0[ss * 64 + tn * 8];
                float4 hb = *(const float4*)&g_h0[ss * 64 + tn * 8 + 4];
                red4(&g_A0[rr2 * 64 + tn * 8],
                     ha.x * o[0], ha.y * o[1], ha.z * o[2], ha.w * o[3]);
                red4(&g_A0[rr2 * 64 + tn * 8 + 4],
                     hb.x * o[4], hb.y * o[5], hb.z * o[6], hb.w * o[7]);
            }
        } else {
#pragma unroll
            for (int j = 0; j < 8; j++) {
                int em = tm * 8 + j;
                size_t eg = (size_t)(blockIdx.x * 256 + em) * 64;
                float o[8];
#pragma unroll
                for (int n = 0; n < 8; n++) {
                    float lo, hi;
                    unpack2(acc[n * 4 + (j >> 1)], lo, hi);
                    o[n] = (j & 1) ? hi : lo;
                }
                *(float4*)&g_R1[eg + tn * 8]     = make_float4(o[0], o[1], o[2], o[3]);
                *(float4*)&g_R1[eg + tn * 8 + 4] = make_float4(o[4], o[5], o[6], o[7]);
            }
        }
    }
}

// ---------- interaction-1 message ----------
__global__ void __launch_bounds__(256)
msg1_kernel(const int* __restrict__ snd, const int* __restrict__ rcv)
{
    unsigned idx = blockIdx.x * 256u + threadIdx.x;
    int e = idx >> 4;
    int q = (idx & 15) * 4;
    int s = snd[e];
    int r = rcv[e];
    float4 R = *(const float4*)&g_R1[(size_t)e * 64 + q];
    float4 h = *(const float4*)&g_h1[s * 64 + q];
    red4(&g_A1[r * 64 + q], h.x * R.x, h.y * R.y, h.z * R.z, h.w * R.w);
}

// ---------- interaction-0 epilogue + out0 + h1 ----------
__global__ void __launch_bounds__(256)
node1_kernel(const float* __restrict__ attrs,
             const float* __restrict__ u0_mix,
             const float* __restrict__ u0_sc,
             const float* __restrict__ u0_prod,
             const float* __restrict__ w_read0,
             const float* __restrict__ u1_up,
             float* __restrict__ out)
{
    __shared__ float sMix[4096];
    __shared__ float sUp1[4096];
    __shared__ float sA[256], semb[256], snf[256], sred[256];

    int tid = threadIdx.x;
    for (int i = tid; i < 4096; i += 256) sMix[i] = u0_mix[i];
    for (int i = tid; i < 4096; i += 256) sUp1[i] = u1_up[i];

    int n = blockIdx.x * 4 + (tid >> 6);
    int g = tid & 63;
    int L = tid & 192;

    sA[tid]   = g_A0[n * 64 + g] * (1.0f / 16.0f);
    semb[tid] = g_emb[n * 64 + g];
    __syncthreads();

    int sp = 0;
#pragma unroll
    for (int s = 0; s < 10; s++)
        if (attrs[n * 10 + s] > 0.5f) sp = s;

    const float* Wsc = u0_sc + sp * 4096;
    float am = 0.f, sc = 0.f;
#pragma unroll 8
    for (int f = 0; f < 64; f++) {
        am += sA[L + f]   * sMix[f * 64 + g];
        sc += semb[L + f] * Wsc[f * 64 + g];
    }
    float p0 = u0_prod[g], p1 = u0_prod[64 + g], p2 = u0_prod[128 + g];
    float nf = am * (p0 + p1 * am + p2 * am * am) + sc;

    g_nf1[n * 64 + g] = nf;
    snf[tid]  = nf;
    sred[tid] = nf * w_read0[g];
    __syncthreads();

    float h = 0.f;
#pragma unroll 8
    for (int f = 0; f < 64; f++)
        h += snf[L + f] * sUp1[f * 64 + g];
    g_h1[n * 64 + g] = h;

    if (g == 0) {
        float t = 0.f;
#pragma unroll
        for (int i = 0; i < 64; i++) t += sred[L + i];
        out[n * 2 + 0] = t;
    }
}

// ---------- interaction-1 epilogue + out1 ----------
__global__ void __launch_bounds__(256)
node2_kernel(const float* __restrict__ attrs,
             const float* __restrict__ u1_mix,
             const float* __restrict__ u1_sc,
             const float* __restrict__ u1_prod,
             const float* __restrict__ w_mlp1,
             const float* __restrict__ w_mlp2,
             float* __restrict__ out)
{
    __shared__ float sMix[4096];
    __shared__ float sM1[1024];
    __shared__ float sA[256], snf1[256], snf2[256], sred[64];

    int tid = threadIdx.x;
    for (int i = tid; i < 4096; i += 256) sMix[i] = u1_mix[i];
    for (int i = tid; i < 1024; i += 256) sM1[i]  = w_mlp1[i];

    int n = blockIdx.x * 4 + (tid >> 6);
    int g = tid & 63;
    int L = tid & 192;

    sA[tid]   = g_A1[n * 64 + g] * (1.0f / 16.0f);
    snf1[tid] = g_nf1[n * 64 + g];
    __syncthreads();

    int sp = 0;
#pragma unroll
    for (int s = 0; s < 10; s++)
        if (attrs[n * 10 + s] > 0.5f) sp = s;

    const float* Wsc = u1_sc + sp * 4096;
    float am = 0.f, sc = 0.f;
#pragma unroll 8
    for (int f = 0; f < 64; f++) {
        am += sA[L + f]   * sMix[f * 64 + g];
        sc += snf1[L + f] * Wsc[f * 64 + g];
    }
    float p0 = u1_prod[g], p1 = u1_prod[64 + g], p2 = u1_prod[128 + g];
    float nf2 = am * (p0 + p1 * am + p2 * am * am) + sc;
    snf2[tid] = nf2;
    __syncthreads();

    if (g < 16) {
        float hv = 0.f;
#pragma unroll 8
        for (int f = 0; f < 64; f++)
            hv += snf2[L + f] * sM1[f * 16 + g];
        sred[(L >> 2) + g] = silu_f(hv) * w_mlp2[g];
    }
    __syncthreads();
    if (g == 0) {
        float t = 0.f;
#pragma unroll
        for (int i = 0; i < 16; i++) t += sred[(L >> 2) + i];
        out[n * 2 + 1] = t;
    }
}

extern "C" void kernel_launch(void* const* d_in, const int* in_sizes, int n_in,
                              void* d_out, int out_size)
{
    const float* positions  = (const float*)d_in[0];
    const float* node_attrs = (const float*)d_in[1];
    const float* shifts     = (const float*)d_in[2];
    const int*   senders    = (const int*)  d_in[3];
    const int*   receivers  = (const int*)  d_in[4];
    const float* w_embed    = (const float*)d_in[5];

    int i_u0 = 6, i_u1, i_read0, i_mlp1, i_mlp2;
    if (in_sizes[13] == 64) {        // signature order
        i_read0 = 13; i_u1 = 14; i_mlp1 = 21; i_mlp2 = 22;
    } else {                          // dict order
        i_u1 = 13; i_read0 = 20; i_mlp1 = 21; i_mlp2 = 22;
    }

    const float* u0_up   = (const float*)d_in[i_u0 + 0];
    const float* u0_r1   = (const float*)d_in[i_u0 + 1];
    const float* u0_r2   = (const float*)d_in[i_u0 + 2];
    const float* u0_r3   = (const float*)d_in[i_u0 + 3];
    const float* u0_mix  = (const float*)d_in[i_u0 + 4];
    const float* u0_sc   = (const float*)d_in[i_u0 + 5];
    const float* u0_prod = (const float*)d_in[i_u0 + 6];
    const float* u1_up   = (const float*)d_in[i_u1 + 0];
    const float* u1_r1   = (const float*)d_in[i_u1 + 1];
    const float* u1_r2   = (const float*)d_in[i_u1 + 2];
    const float* u1_r3   = (const float*)d_in[i_u1 + 3];
    const float* u1_mix  = (const float*)d_in[i_u1 + 4];
    const float* u1_sc   = (const float*)d_in[i_u1 + 5];
    const float* u1_prod = (const float*)d_in[i_u1 + 6];
    const float* w_read0 = (const float*)d_in[i_read0];
    const float* w_mlp1  = (const float*)d_in[i_mlp1];
    const float* w_mlp2  = (const float*)d_in[i_mlp2];

    float* out = (float*)d_out;

    cudaFuncSetAttribute(edge_fused,
                         cudaFuncAttributeMaxDynamicSharedMemorySize, 102400);

    node_init_kernel<<<Nn / 4, 256>>>(node_attrs, w_embed, u0_up);
    edge_fused<<<Ee / 256, 256, 102400>>>(positions, shifts, senders, receivers,
                                          u0_r1, u0_r2, u0_r3,
                                          u1_r1, u1_r2, u1_r3);
    node1_kernel<<<Nn / 4, 256>>>(node_attrs, u0_mix, u0_sc, u0_prod,
                                  w_read0, u1_up, out);
    msg1_kernel<<<Ee * 16 / 256, 256>>>(senders, receivers);
    node2_kernel<<<Nn / 4, 256>>>(node_attrs, u1_mix, u1_sc, u1_prod,
                                  w_mlp1, w_mlp2, out);
}

// round 5
// speedup vs baseline: 2.5452x; 2.0167x over previous
#include <cuda_runtime.h>
#include <math.h>

#define Nn 10000
#define Ee 160000
#define NT 8192          // radial table resolution over [0, 10]

// ---------- device scratch ----------
__device__ float  g_emb[Nn * 64];
__device__ float  g_h0 [Nn * 64];
__device__ float  g_h1 [Nn * 64];
__device__ float  g_A0 [Nn * 64];
__device__ float  g_A1 [Nn * 64];
__device__ float  g_nf1[Nn * 64];
__device__ float  g_T0 [NT * 64];    // tabulated l=0 radial function, interaction 0
__device__ float  g_T1 [NT * 64];    // interaction 1
__device__ float2 g_rx [Ee];         // per-edge (table index bits, frac)

__device__ __forceinline__ void red4(float* p, float a, float b, float c, float d) {
    asm volatile("red.global.add.v4.f32 [%0], {%1, %2, %3, %4};"
                 :: "l"(p), "f"(a), "f"(b), "f"(c), "f"(d) : "memory");
}
__device__ __forceinline__ float silu_f(float x) {
    return x / (1.0f + __expf(-x));
}

// ---------- node init: emb = attrs @ w_embed ; h0 = emb @ u0_up ; zero A ----------
__global__ void __launch_bounds__(256)
node_init_kernel(const float* __restrict__ attrs,
                 const float* __restrict__ w_embed,
                 const float* __restrict__ u0_up)
{
    __shared__ float sUp[4096];
    __shared__ float sWe[640];
    __shared__ float semb[256];
    int tid = threadIdx.x;
    for (int i = tid; i < 4096; i += 256) sUp[i] = u0_up[i];
    for (int i = tid; i < 640;  i += 256) sWe[i] = w_embed[i];
    __syncthreads();

    int n = blockIdx.x * 4 + (tid >> 6);
    int g = tid & 63;

    float v = 0.f;
#pragma unroll
    for (int s = 0; s < 10; s++)
        v += attrs[n * 10 + s] * sWe[s * 64 + g];
    semb[tid] = v;
    g_emb[n * 64 + g] = v;
    g_A0[n * 64 + g] = 0.f;
    g_A1[n * 64 + g] = 0.f;
    __syncthreads();

    const float* se = &semb[tid & 192];
    float h = 0.f;
#pragma unroll 8
    for (int f = 0; f < 64; f++)
        h += se[f] * sUp[f * 64 + g];
    g_h0[n * 64 + g] = h;
}

// ---------- per-edge geometry: r -> (table index, frac) ----------
__global__ void __launch_bounds__(256)
geom_kernel(const float* __restrict__ pos,
            const float* __restrict__ shifts,
            const int*   __restrict__ snd,
            const int*   __restrict__ rcv)
{
    int e = blockIdx.x * 256 + threadIdx.x;
    if (e >= Ee) return;
    int s = snd[e];
    int r = rcv[e];
    float dx = pos[3 * r + 0] - pos[3 * s + 0] + shifts[3 * e + 0];
    float dy = pos[3 * r + 1] - pos[3 * s + 1] + shifts[3 * e + 1];
    float dz = pos[3 * r + 2] - pos[3 * s + 2] + shifts[3 * e + 2];
    float rr = sqrtf(dx * dx + dy * dy + dz * dz);

    float t  = rr * ((float)NT / 10.0f);
    int   i0 = (int)t;
    if (i0 > NT - 2) i0 = NT - 2;
    float fr = t - (float)i0;
    g_rx[e] = make_float2(__int_as_float(i0), fr);
}

// ---------- tabulate the exact radial MLP (l=0 channel) on the grid ----------
// one block of 64 threads per grid point; both interactions per block
__global__ void __launch_bounds__(64)
tab_kernel(const float* __restrict__ W1a, const float* __restrict__ W2a,
           const float* __restrict__ W3a,
           const float* __restrict__ W1b, const float* __restrict__ W2b,
           const float* __restrict__ W3b)
{
    int p = blockIdx.x;
    int f = threadIdx.x;
    __shared__ float l1[64], t2[64];

    float rr = (float)p * (10.0f / (float)NT);

    float inv = 1.0f / (rr + 1e-9f);
    float xr  = rr * 0.1f;
    float xr2 = xr * xr;
    float x5  = xr2 * xr2 * xr;
    float env = 1.0f - 21.0f * x5 + 35.0f * x5 * xr - 15.0f * x5 * xr2;
    if (xr >= 1.0f) env = 0.0f;
    float scl   = 0.44721359549995793f * inv * env;
    float theta = 3.14159265358979323846f * xr;

    float b[8];
#pragma unroll
    for (int k = 0; k < 8; k++)
        b[k] = scl * sinf((float)(k + 1) * theta);

#pragma unroll 1
    for (int phase = 0; phase < 2; phase++) {
        const float* W1 = phase ? W1b : W1a;
        const float* W2 = phase ? W2b : W2a;
        const float* W3 = phase ? W3b : W3a;
        float* T = phase ? g_T1 : g_T0;

        float v = 0.f;
#pragma unroll
        for (int k = 0; k < 8; k++)
            v += b[k] * W1[k * 64 + f];
        l1[f] = silu_f(v);
        __syncthreads();

        float w = 0.f;
#pragma unroll 8
        for (int i = 0; i < 64; i++)
            w += l1[i] * W2[i * 64 + f];
        t2[f] = silu_f(w);
        __syncthreads();

        float o = 0.f;
#pragma unroll 8
        for (int j = 0; j < 64; j++)
            o += t2[j] * W3[j * 256 + 4 * f];   // l=0 column
        T[p * 64 + f] = o;

        __syncthreads();   // protect l1/t2 before next phase overwrites
    }
}

// ---------- edge message pass via table interpolation ----------
// PHASE 0: m = h0[s] * lerp(T0) -> RED into A0
// PHASE 1: m = h1[s] * lerp(T1) -> RED into A1
template <int PHASE>
__global__ void __launch_bounds__(256)
edge_pass(const int* __restrict__ snd, const int* __restrict__ rcv)
{
    unsigned idx = blockIdx.x * 256u + threadIdx.x;   // Ee*16 threads
    int e = idx >> 4;
    int q = (idx & 15) * 4;

    int s = snd[e];
    int r = rcv[e];
    float2 rx = g_rx[e];
    int   i0 = __float_as_int(rx.x);
    float fr = rx.y;

    const float* T = PHASE ? g_T1 : g_T0;
    const float* H = PHASE ? g_h1 : g_h0;
    float*       A = PHASE ? g_A1 : g_A0;

    float4 ta = *(const float4*)&T[i0 * 64 + q];
    float4 tb = *(const float4*)&T[(i0 + 1) * 64 + q];
    float4 h  = *(const float4*)&H[s * 64 + q];

    float R0 = ta.x + fr * (tb.x - ta.x);
    float R1 = ta.y + fr * (tb.y - ta.y);
    float R2 = ta.z + fr * (tb.z - ta.z);
    float R3 = ta.w + fr * (tb.w - ta.w);

    red4(&A[r * 64 + q], h.x * R0, h.y * R1, h.z * R2, h.w * R3);
}

// ---------- interaction-0 epilogue + out0 + h1 ----------
__global__ void __launch_bounds__(256)
node1_kernel(const float* __restrict__ attrs,
             const float* __restrict__ u0_mix,
             const float* __restrict__ u0_sc,
             const float* __restrict__ u0_prod,
             const float* __restrict__ w_read0,
             const float* __restrict__ u1_up,
             float* __restrict__ out)
{
    __shared__ float sMix[4096];
    __shared__ float sUp1[4096];
    __shared__ float sA[256], semb[256], snf[256], sred[256];

    int tid = threadIdx.x;
    for (int i = tid; i < 4096; i += 256) sMix[i] = u0_mix[i];
    for (int i = tid; i < 4096; i += 256) sUp1[i] = u1_up[i];

    int n = blockIdx.x * 4 + (tid >> 6);
    int g = tid & 63;
    int L = tid & 192;

    sA[tid]   = g_A0[n * 64 + g] * (1.0f / 16.0f);
    semb[tid] = g_emb[n * 64 + g];
    __syncthreads();

    int sp = 0;
#pragma unroll
    for (int s = 0; s < 10; s++)
        if (attrs[n * 10 + s] > 0.5f) sp = s;

    const float* Wsc = u0_sc + sp * 4096;
    float am = 0.f, sc = 0.f;
#pragma unroll 8
    for (int f = 0; f < 64; f++) {
        am += sA[L + f]   * sMix[f * 64 + g];
        sc += semb[L + f] * Wsc[f * 64 + g];
    }
    float p0 = u0_prod[g], p1 = u0_prod[64 + g], p2 = u0_prod[128 + g];
    float nf = am * (p0 + p1 * am + p2 * am * am) + sc;

    g_nf1[n * 64 + g] = nf;
    snf[tid]  = nf;
    sred[tid] = nf * w_read0[g];
    __syncthreads();

    float h = 0.f;
#pragma unroll 8
    for (int f = 0; f < 64; f++)
        h += snf[L + f] * sUp1[f * 64 + g];
    g_h1[n * 64 + g] = h;

    if (g == 0) {
        float t = 0.f;
#pragma unroll
        for (int i = 0; i < 64; i++) t += sred[L + i];
        out[n * 2 + 0] = t;
    }
}

// ---------- interaction-1 epilogue + out1 ----------
__global__ void __launch_bounds__(256)
node2_kernel(const float* __restrict__ attrs,
             const float* __restrict__ u1_mix,
             const float* __restrict__ u1_sc,
             const float* __restrict__ u1_prod,
             const float* __restrict__ w_mlp1,
             const float* __restrict__ w_mlp2,
             float* __restrict__ out)
{
    __shared__ float sMix[4096];
    __shared__ float sM1[1024];
    __shared__ float sA[256], snf1[256], snf2[256], sred[64];

    int tid = threadIdx.x;
    for (int i = tid; i < 4096; i += 256) sMix[i] = u1_mix[i];
    for (int i = tid; i < 1024; i += 256) sM1[i]  = w_mlp1[i];

    int n = blockIdx.x * 4 + (tid >> 6);
    int g = tid & 63;
    int L = tid & 192;

    sA[tid]   = g_A1[n * 64 + g] * (1.0f / 16.0f);
    snf1[tid] = g_nf1[n * 64 + g];
    __syncthreads();

    int sp = 0;
#pragma unroll
    for (int s = 0; s < 10; s++)
        if (attrs[n * 10 + s] > 0.5f) sp = s;

    const float* Wsc = u1_sc + sp * 4096;
    float am = 0.f, sc = 0.f;
#pragma unroll 8
    for (int f = 0; f < 64; f++) {
        am += sA[L + f]   * sMix[f * 64 + g];
        sc += snf1[L + f] * Wsc[f * 64 + g];
    }
    float p0 = u1_prod[g], p1 = u1_prod[64 + g], p2 = u1_prod[128 + g];
    float nf2 = am * (p0 + p1 * am + p2 * am * am) + sc;
    snf2[tid] = nf2;
    __syncthreads();

    if (g < 16) {
        float hv = 0.f;
#pragma unroll 8
        for (int f = 0; f < 64; f++)
            hv += snf2[L + f] * sM1[f * 16 + g];
        sred[(L >> 2) + g] = silu_f(hv) * w_mlp2[g];
    }
    __syncthreads();
    if (g == 0) {
        float t = 0.f;
#pragma unroll
        for (int i = 0; i < 16; i++) t += sred[(L >> 2) + i];
        out[n * 2 + 1] = t;
    }
}

extern "C" void kernel_launch(void* const* d_in, const int* in_sizes, int n_in,
                              void* d_out, int out_size)
{
    const float* positions  = (const float*)d_in[0];
    const float* node_attrs = (const float*)d_in[1];
    const float* shifts     = (const float*)d_in[2];
    const int*   senders    = (const int*)  d_in[3];
    const int*   receivers  = (const int*)  d_in[4];
    const float* w_embed    = (const float*)d_in[5];

    int i_u0 = 6, i_u1, i_read0, i_mlp1, i_mlp2;
    if (in_sizes[13] == 64) {        // signature order
        i_read0 = 13; i_u1 = 14; i_mlp1 = 21; i_mlp2 = 22;
    } else {                          // dict order
        i_u1 = 13; i_read0 = 20; i_mlp1 = 21; i_mlp2 = 22;
    }

    const float* u0_up   = (const float*)d_in[i_u0 + 0];
    const float* u0_r1   = (const float*)d_in[i_u0 + 1];
    const float* u0_r2   = (const float*)d_in[i_u0 + 2];
    const float* u0_r3   = (const float*)d_in[i_u0 + 3];
    const float* u0_mix  = (const float*)d_in[i_u0 + 4];
    const float* u0_sc   = (const float*)d_in[i_u0 + 5];
    const float* u0_prod = (const float*)d_in[i_u0 + 6];
    const float* u1_up   = (const float*)d_in[i_u1 + 0];
    const float* u1_r1   = (const float*)d_in[i_u1 + 1];
    const float* u1_r2   = (const float*)d_in[i_u1 + 2];
    const float* u1_r3   = (const float*)d_in[i_u1 + 3];
    const float* u1_mix  = (const float*)d_in[i_u1 + 4];
    const float* u1_sc   = (const float*)d_in[i_u1 + 5];
    const float* u1_prod = (const float*)d_in[i_u1 + 6];
    const float* w_read0 = (const float*)d_in[i_read0];
    const float* w_mlp1  = (const float*)d_in[i_mlp1];
    const float* w_mlp2  = (const float*)d_in[i_mlp2];

    float* out = (float*)d_out;

    node_init_kernel<<<Nn / 4, 256>>>(node_attrs, w_embed, u0_up);
    geom_kernel<<<(Ee + 255) / 256, 256>>>(positions, shifts, senders, receivers);
    tab_kernel<<<NT, 64>>>(u0_r1, u0_r2, u0_r3, u1_r1, u1_r2, u1_r3);
    edge_pass<0><<<Ee * 16 / 256, 256>>>(senders, receivers);
    node1_kernel<<<Nn / 4, 256>>>(node_attrs, u0_mix, u0_sc, u0_prod,
                                  w_read0, u1_up, out);
    edge_pass<1><<<Ee * 16 / 256, 256>>>(senders, receivers);
    node2_kernel<<<Nn / 4, 256>>>(node_attrs, u1_mix, u1_sc, u1_prod,
                                  w_mlp1, w_mlp2, out);
}